// round 8
// baseline (speedup 1.0000x reference)
#include <cuda_runtime.h>
#include <cuda_bf16.h>
#include <cuda_fp16.h>
#include <mma.h>
using namespace nvcuda;

// Problem constants (fixed by the reference)
#define NN 20000
#define EE 320000
#define ET (NN + EE)          // edges incl. self loops = 340000
#define HEADS 8
#define MP 20096              // NN padded to multiple of 128 for tensor GEMM
#define NBLK ((NN + 255) / 256)   // 79 blocks for CSR scan

// ---------------- scratch (device globals: no allocation allowed) ----------
__device__ float g_feat[(size_t)MP * 1024];   // transformed features (fp32)
__device__ __half g_feath[(size_t)MP * 1024]; // fp16 shadow for gathers
__device__ float g_accb[(size_t)NN * 256];    // aggregation output
__device__ float g_act0[(size_t)NN * 256];    // activation after layer 0
__device__ float g_act1[(size_t)NN * 256];    // activation after layer 1
__device__ float g_resb[(size_t)MP * 256];    // residual projection
__device__ float g_als[NN * HEADS];
__device__ float g_ald[NN * HEADS];
__device__ int g_src[ET];
__device__ int g_dst[ET];
__device__ int g_is64;
// CSR (dst-sorted adjacency)
__device__ int g_deg[NN];
__device__ int g_off[NN + 1];
__device__ int g_cur[NN];
__device__ int g_csr_src[ET];
__device__ int g_bsum[NBLK];
__device__ int g_boff[NBLK];

// bf16 split buffers for tensor-core GEMM
__device__ __nv_bfloat16 g_Ah[(size_t)MP * 256];
__device__ __nv_bfloat16 g_Al[(size_t)MP * 256];
__device__ __nv_bfloat16 g_Bh[256 * 1024];
__device__ __nv_bfloat16 g_Bl[256 * 1024];

// ---------------- dtype detection: int64 vs int32 edge_index ---------------
__global__ void detect_kernel(const int* __restrict__ raw) {
    __shared__ int any;
    if (threadIdx.x == 0) any = 0;
    __syncthreads();
    for (int i = threadIdx.x; i < 2048; i += blockDim.x)
        if (raw[2 * i + 1] != 0) any = 1;
    __syncthreads();
    if (threadIdx.x == 0) g_is64 = (any == 0);
}

// ---------------- edge list build (append self loops), zero degrees --------
__global__ void build_edges_kernel(const void* __restrict__ eiraw) {
    int i = blockIdx.x * blockDim.x + threadIdx.x;
    if (i < NN) g_deg[i] = 0;
    if (i >= ET) return;
    int s, d;
    if (i < EE) {
        if (g_is64) {
            const long long* e = (const long long*)eiraw;
            s = (int)e[i];
            d = (int)e[EE + i];
        } else {
            const int* e = (const int*)eiraw;
            s = e[i];
            d = e[EE + i];
        }
        s = min(max(s, 0), NN - 1);
        d = min(max(d, 0), NN - 1);
    } else {
        s = d = i - EE;   // self loop
    }
    g_src[i] = s;
    g_dst[i] = d;
}

// ---------------- CSR build: histogram, 3-phase parallel scan, scatter -----
__global__ void hist_kernel() {
    int i = blockIdx.x * blockDim.x + threadIdx.x;
    if (i < ET) atomicAdd(&g_deg[g_dst[i]], 1);
}

// phase 1: per-block sums of 256 degrees
__global__ void csr_partial_kernel() {
    __shared__ int sh[256];
    int idx = blockIdx.x * 256 + threadIdx.x;
    int v = (idx < NN) ? g_deg[idx] : 0;
    sh[threadIdx.x] = v;
    __syncthreads();
    for (int off = 128; off; off >>= 1) {
        if (threadIdx.x < off) sh[threadIdx.x] += sh[threadIdx.x + off];
        __syncthreads();
    }
    if (threadIdx.x == 0) g_bsum[blockIdx.x] = sh[0];
}

// phase 2: exclusive scan of NBLK block sums (tiny)
__global__ void csr_scanb_kernel() {
    if (threadIdx.x == 0) {
        int run = 0;
        for (int i = 0; i < NBLK; i++) { g_boff[i] = run; run += g_bsum[i]; }
        g_off[NN] = ET;
    }
}

// phase 3: per-block exclusive scan + base offset
__global__ void csr_offsets_kernel() {
    __shared__ int sh[256];
    int idx = blockIdx.x * 256 + threadIdx.x;
    int v = (idx < NN) ? g_deg[idx] : 0;
    sh[threadIdx.x] = v;
    __syncthreads();
    for (int off = 1; off < 256; off <<= 1) {
        int u = (threadIdx.x >= off) ? sh[threadIdx.x - off] : 0;
        __syncthreads();
        sh[threadIdx.x] += u;
        __syncthreads();
    }
    if (idx < NN) {
        int excl = g_boff[blockIdx.x] + sh[threadIdx.x] - v;
        g_off[idx] = excl;
        g_cur[idx] = excl;
    }
}

__global__ void scatter_kernel() {
    int i = blockIdx.x * blockDim.x + threadIdx.x;
    if (i >= ET) return;
    int d = g_dst[i];
    int pos = atomicAdd(&g_cur[d], 1);
    g_csr_src[pos] = g_src[i];
}

// ---------------- zero bf16 split padding rows (once per launch) -----------
__global__ void pad_kernel() {
    int i = blockIdx.x * blockDim.x + threadIdx.x;
    int tot = (MP - NN) * 256;
    if (i < tot) {
        g_Ah[(size_t)NN * 256 + i] = __float2bfloat16(0.f);
        g_Al[(size_t)NN * 256 + i] = __float2bfloat16(0.f);
    }
}

// ---------------- fp32 -> bf16 hi/lo split (vectorized x4) ------------------
__global__ void split_kernel(const float* __restrict__ X,
                             __nv_bfloat16* __restrict__ H,
                             __nv_bfloat16* __restrict__ L,
                             int realElems, int totElems) {
    int i = (blockIdx.x * blockDim.x + threadIdx.x) * 4;
    if (i >= totElems) return;
    float4 v = (i < realElems) ? *(const float4*)&X[i] : make_float4(0.f, 0.f, 0.f, 0.f);
    __nv_bfloat162 h01 = {__float2bfloat16(v.x), __float2bfloat16(v.y)};
    __nv_bfloat162 h23 = {__float2bfloat16(v.z), __float2bfloat16(v.w)};
    __nv_bfloat162 l01 = {__float2bfloat16(v.x - __bfloat162float(h01.x)),
                          __float2bfloat16(v.y - __bfloat162float(h01.y))};
    __nv_bfloat162 l23 = {__float2bfloat16(v.z - __bfloat162float(h23.x)),
                          __float2bfloat16(v.w - __bfloat162float(h23.y))};
    *(__nv_bfloat162*)&H[i] = h01;
    *(__nv_bfloat162*)&H[i + 2] = h23;
    *(__nv_bfloat162*)&L[i] = l01;
    *(__nv_bfloat162*)&L[i + 2] = l23;
}

// ---------------- fp32 -> fp16 plain convert (for gather shadow) -----------
__global__ void tohalf_kernel(const float* __restrict__ X,
                              __half* __restrict__ Y, int elems) {
    int i = (blockIdx.x * blockDim.x + threadIdx.x) * 4;
    if (i >= elems) return;
    float4 v = *(const float4*)&X[i];
    __half2 a = __floats2half2_rn(v.x, v.y);
    __half2 b = __floats2half2_rn(v.z, v.w);
    *(__half2*)&Y[i] = a;
    *(__half2*)&Y[i + 2] = b;
}

// ---------------- tensor-core GEMM: C[MP,N] = A[MP,K] @ B[K,N] -------------
struct __align__(256) SmemA { __nv_bfloat16 d[128][40]; };
struct __align__(256) SmemB { __nv_bfloat16 d[32][136]; };

__global__ void __launch_bounds__(256) gemm_tc_kernel(
    const __nv_bfloat16* __restrict__ Ah, const __nv_bfloat16* __restrict__ Al,
    const __nv_bfloat16* __restrict__ Bh, const __nv_bfloat16* __restrict__ Bl,
    float* __restrict__ C, int N, int K)
{
    __shared__ SmemA sAh, sAl;
    __shared__ SmemB sBh, sBl;
    int tid = threadIdx.x;
    int warp = tid >> 5;
    int wm = warp & 1, wn = warp >> 1;           // 2 x 4 warp grid
    int row0 = blockIdx.y * 128, col0 = blockIdx.x * 128;

    wmma::fragment<wmma::accumulator, 16, 16, 16, float> acc[4][2];
#pragma unroll
    for (int i = 0; i < 4; i++)
#pragma unroll
        for (int j = 0; j < 2; j++) wmma::fill_fragment(acc[i][j], 0.f);

    for (int k0 = 0; k0 < K; k0 += 32) {
#pragma unroll
        for (int v = tid; v < 512; v += 256) {
            int r = v >> 2, kk = (v & 3) * 8;
            size_t g = (size_t)(row0 + r) * K + k0 + kk;
            *(uint4*)&sAh.d[r][kk] = *(const uint4*)&Ah[g];
            *(uint4*)&sAl.d[r][kk] = *(const uint4*)&Al[g];
        }
#pragma unroll
        for (int v = tid; v < 512; v += 256) {
            int r = v >> 4, cc = (v & 15) * 8;
            size_t g = (size_t)(k0 + r) * N + col0 + cc;
            *(uint4*)&sBh.d[r][cc] = *(const uint4*)&Bh[g];
            *(uint4*)&sBl.d[r][cc] = *(const uint4*)&Bl[g];
        }
        __syncthreads();
#pragma unroll
        for (int ks = 0; ks < 32; ks += 16) {
            wmma::fragment<wmma::matrix_a, 16, 16, 16, __nv_bfloat16, wmma::row_major> fah[4], fal[4];
            wmma::fragment<wmma::matrix_b, 16, 16, 16, __nv_bfloat16, wmma::row_major> fbh[2], fbl[2];
#pragma unroll
            for (int i = 0; i < 4; i++) {
                wmma::load_matrix_sync(fah[i], &sAh.d[wm * 64 + i * 16][ks], 40);
                wmma::load_matrix_sync(fal[i], &sAl.d[wm * 64 + i * 16][ks], 40);
            }
#pragma unroll
            for (int j = 0; j < 2; j++) {
                wmma::load_matrix_sync(fbh[j], &sBh.d[ks][wn * 32 + j * 16], 136);
                wmma::load_matrix_sync(fbl[j], &sBl.d[ks][wn * 32 + j * 16], 136);
            }
#pragma unroll
            for (int i = 0; i < 4; i++)
#pragma unroll
                for (int j = 0; j < 2; j++) {
                    wmma::mma_sync(acc[i][j], fah[i], fbh[j], acc[i][j]);
                    wmma::mma_sync(acc[i][j], fal[i], fbh[j], acc[i][j]);
                    wmma::mma_sync(acc[i][j], fah[i], fbl[j], acc[i][j]);
                }
        }
        __syncthreads();
    }
#pragma unroll
    for (int i = 0; i < 4; i++)
#pragma unroll
        for (int j = 0; j < 2; j++)
            wmma::store_matrix_sync(&C[(size_t)(row0 + wm * 64 + i * 16) * N +
                                       col0 + wn * 32 + j * 16],
                                    acc[i][j], N, wmma::mem_row_major);
}

// ---------------- attention logits: al_s/al_d per (node, head) -------------
__global__ void al_kernel(const float* __restrict__ a_s, const float* __restrict__ a_d, int C) {
    int idx = blockIdx.x * blockDim.x + threadIdx.x;
    if (idx >= NN * HEADS) return;
    int n = idx >> 3, h = idx & 7;
    const float* f = g_feat + (size_t)n * HEADS * C + h * C;
    const float* w1 = a_s + h * C;
    const float* w2 = a_d + h * C;
    float s1 = 0.f, s2 = 0.f;
    for (int c = 0; c < C; c++) { float v = f[c]; s1 += v * w1[c]; s2 += v * w2[c]; }
    g_als[idx] = s1;
    g_ald[idx] = s2;
}

// ---------------- fused aggregation (layers 0/1, C=32), warp per dst -------
// fp16 feature gather (half the L2 traffic); alphas from fp32 logits.
__global__ void __launch_bounds__(256) agg_small_kernel(const __half* __restrict__ feath,
                                                        float* __restrict__ out) {
    int wid = (blockIdx.x * blockDim.x + threadIdx.x) >> 5;
    if (wid >= NN) return;
    int lane = threadIdx.x & 31;
    int h = lane & 7;
    int beg = g_off[wid], end = g_off[wid + 1];
    float ald_h = g_ald[wid * HEADS + h];

    // Pass A: max
    float m = -1e30f;
    for (int i = beg + (lane >> 3); i < end; i += 4) {
        int s = g_csr_src[i];
        float ev = g_als[s * HEADS + h] + ald_h;
        ev = ev > 0.f ? ev : 0.2f * ev;
        m = fmaxf(m, ev);
    }
    m = fmaxf(m, __shfl_xor_sync(0xffffffffu, m, 8));
    m = fmaxf(m, __shfl_xor_sync(0xffffffffu, m, 16));
    // Pass A: denom
    float ssum = 0.f;
    for (int i = beg + (lane >> 3); i < end; i += 4) {
        int s = g_csr_src[i];
        float ev = g_als[s * HEADS + h] + ald_h;
        ev = ev > 0.f ? ev : 0.2f * ev;
        ssum += expf(ev - m);
    }
    ssum += __shfl_xor_sync(0xffffffffu, ssum, 8);
    ssum += __shfl_xor_sync(0xffffffffu, ssum, 16);
    float inv = 1.f / (ssum + 1e-16f);

    // Pass B: gather + accumulate
    float acc[8] = {0.f, 0.f, 0.f, 0.f, 0.f, 0.f, 0.f, 0.f};
    for (int i = beg; i < end; i++) {
        int s = g_csr_src[i];
        float ev = g_als[s * HEADS + h] + ald_h;
        ev = ev > 0.f ? ev : 0.2f * ev;
        float alpha = expf(ev - m) * inv;       // lane hh holds alpha for head hh
        const __half* f = feath + (size_t)s * 256;
#pragma unroll
        for (int hh = 0; hh < 8; hh++) {
            float a = __shfl_sync(0xffffffffu, alpha, hh);
            acc[hh] += a * __half2float(f[hh * 32 + lane]);
        }
    }
    float* o = out + (size_t)wid * 256;
#pragma unroll
    for (int hh = 0; hh < 8; hh++) o[hh * 32 + lane] = acc[hh];
}

// ---------------- fused aggregation (layer 2, C=128, mean over heads) ------
__global__ void __launch_bounds__(256) agg_big_kernel(const __half* __restrict__ feath,
                                                      float* __restrict__ out) {
    int wid = (blockIdx.x * blockDim.x + threadIdx.x) >> 5;
    if (wid >= NN) return;
    int lane = threadIdx.x & 31;
    int h = lane & 7;
    int beg = g_off[wid], end = g_off[wid + 1];
    float ald_h = g_ald[wid * HEADS + h];

    float m = -1e30f;
    for (int i = beg + (lane >> 3); i < end; i += 4) {
        int s = g_csr_src[i];
        float ev = g_als[s * HEADS + h] + ald_h;
        ev = ev > 0.f ? ev : 0.2f * ev;
        m = fmaxf(m, ev);
    }
    m = fmaxf(m, __shfl_xor_sync(0xffffffffu, m, 8));
    m = fmaxf(m, __shfl_xor_sync(0xffffffffu, m, 16));
    float ssum = 0.f;
    for (int i = beg + (lane >> 3); i < end; i += 4) {
        int s = g_csr_src[i];
        float ev = g_als[s * HEADS + h] + ald_h;
        ev = ev > 0.f ? ev : 0.2f * ev;
        ssum += expf(ev - m);
    }
    ssum += __shfl_xor_sync(0xffffffffu, ssum, 8);
    ssum += __shfl_xor_sync(0xffffffffu, ssum, 16);
    float inv = 0.125f / (ssum + 1e-16f);       // fold mean-over-heads

    float acc[4] = {0.f, 0.f, 0.f, 0.f};
    for (int i = beg; i < end; i++) {
        int s = g_csr_src[i];
        float ev = g_als[s * HEADS + h] + ald_h;
        ev = ev > 0.f ? ev : 0.2f * ev;
        float alpha = expf(ev - m) * inv;
        const __half* f = feath + (size_t)s * 1024;
#pragma unroll
        for (int hh = 0; hh < 8; hh++) {
            float a = __shfl_sync(0xffffffffu, alpha, hh);
            const __half* fh = f + hh * 128;
#pragma unroll
            for (int ch = 0; ch < 4; ch++)
                acc[ch] += a * __half2float(fh[ch * 32 + lane]);
        }
    }
    float* o = out + (size_t)wid * 128;
#pragma unroll
    for (int ch = 0; ch < 4; ch++) o[ch * 32 + lane] = acc[ch];
}

// ---------------- finalize layers 0/1: +bias, LN, +sig*res, ELU + split ----
__global__ void finalize01_kernel(const float* __restrict__ bias,
                                  const float* __restrict__ lng, const float* __restrict__ lnb,
                                  const float* __restrict__ res, const float* __restrict__ rb,
                                  const float* __restrict__ rw, float* __restrict__ out,
                                  __nv_bfloat16* __restrict__ outH,
                                  __nv_bfloat16* __restrict__ outL) {
    int n = blockIdx.x, t = threadIdx.x;   // 256 threads
    float g = g_accb[(size_t)n * 256 + t] + bias[t];
    float s1 = g, s2 = g * g;
#pragma unroll
    for (int o = 16; o; o >>= 1) {
        s1 += __shfl_down_sync(0xffffffffu, s1, o);
        s2 += __shfl_down_sync(0xffffffffu, s2, o);
    }
    __shared__ float sh1[8], sh2[8];
    __shared__ float mu_s, rs_s;
    int w = t >> 5, l = t & 31;
    if (l == 0) { sh1[w] = s1; sh2[w] = s2; }
    __syncthreads();
    if (t == 0) {
        float a = 0.f, b = 0.f;
#pragma unroll
        for (int i = 0; i < 8; i++) { a += sh1[i]; b += sh2[i]; }
        float mu = a * (1.f / 256.f);
        float var = b * (1.f / 256.f) - mu * mu;
        mu_s = mu;
        rs_s = rsqrtf(var + 1e-5f);
    }
    __syncthreads();
    float y = (g - mu_s) * rs_s * lng[t] + lnb[t];
    float sig = 1.f / (1.f + expf(-rw[0]));
    float r = res[(size_t)n * 256 + t];
    if (rb) r += rb[t];
    float z = y + sig * r;
    z = z > 0.f ? z : expm1f(z);   // elu
    size_t o = (size_t)n * 256 + t;
    out[o] = z;
    __nv_bfloat16 zh = __float2bfloat16(z);
    outH[o] = zh;
    outL[o] = __float2bfloat16(z - __bfloat162float(zh));
}

// ---------------- finalize layer 2: +bias, LN, +sig*res (no elu) -----------
__global__ void finalize2_kernel(const float* __restrict__ bias,
                                 const float* __restrict__ lng, const float* __restrict__ lnb,
                                 const float* __restrict__ res, const float* __restrict__ rb,
                                 const float* __restrict__ rw, float* __restrict__ out) {
    int n = blockIdx.x, t = threadIdx.x;   // 128 threads
    float g = g_accb[(size_t)n * 128 + t] + bias[t];
    float s1 = g, s2 = g * g;
#pragma unroll
    for (int o = 16; o; o >>= 1) {
        s1 += __shfl_down_sync(0xffffffffu, s1, o);
        s2 += __shfl_down_sync(0xffffffffu, s2, o);
    }
    __shared__ float sh1[4], sh2[4];
    __shared__ float mu_s, rs_s;
    int w = t >> 5, l = t & 31;
    if (l == 0) { sh1[w] = s1; sh2[w] = s2; }
    __syncthreads();
    if (t == 0) {
        float a = 0.f, b = 0.f;
#pragma unroll
        for (int i = 0; i < 4; i++) { a += sh1[i]; b += sh2[i]; }
        float mu = a * (1.f / 128.f);
        float var = b * (1.f / 128.f) - mu * mu;
        mu_s = mu;
        rs_s = rsqrtf(var + 1e-5f);
    }
    __syncthreads();
    float y = (g - mu_s) * rs_s * lng[t] + lnb[t];
    float sig = 1.f / (1.f + expf(-rw[0]));
    float r = res[(size_t)n * 128 + t] + rb[t];
    out[(size_t)n * 128 + t] = y + sig * r;
}

// ---------------------------------------------------------------------------
extern "C" void kernel_launch(void* const* d_in, const int* in_sizes, int n_in,
                              void* d_out, int out_size) {
    const float* x   = (const float*)d_in[0];
    const void*  ei  = d_in[1];                   // int32 or int64, detected on device
    const float* W0  = (const float*)d_in[2];
    const float* b0  = (const float*)d_in[3];
    const float* as0 = (const float*)d_in[4];
    const float* ad0 = (const float*)d_in[5];
    const float* lng0= (const float*)d_in[6];
    const float* lnb0= (const float*)d_in[7];
    const float* rW0 = (const float*)d_in[8];
    const float* rb0 = (const float*)d_in[9];
    const float* rw0 = (const float*)d_in[10];
    const float* W1  = (const float*)d_in[11];
    const float* b1  = (const float*)d_in[12];
    const float* as1 = (const float*)d_in[13];
    const float* ad1 = (const float*)d_in[14];
    const float* lng1= (const float*)d_in[15];
    const float* lnb1= (const float*)d_in[16];
    const float* rw1 = (const float*)d_in[17];
    const float* W2  = (const float*)d_in[18];
    const float* b2  = (const float*)d_in[19];
    const float* as2 = (const float*)d_in[20];
    const float* ad2 = (const float*)d_in[21];
    const float* lng2= (const float*)d_in[22];
    const float* lnb2= (const float*)d_in[23];
    const float* rW2 = (const float*)d_in[24];
    const float* rb2 = (const float*)d_in[25];
    const float* rw2 = (const float*)d_in[26];

    float *feat, *act0, *act1, *res, *accb;
    __half *feath;
    __nv_bfloat16 *Ah, *Al, *Bh, *Bl;
    cudaGetSymbolAddress((void**)&feat, g_feat);
    cudaGetSymbolAddress((void**)&feath, g_feath);
    cudaGetSymbolAddress((void**)&act0, g_act0);
    cudaGetSymbolAddress((void**)&act1, g_act1);
    cudaGetSymbolAddress((void**)&res,  g_resb);
    cudaGetSymbolAddress((void**)&accb, g_accb);
    cudaGetSymbolAddress((void**)&Ah, g_Ah);
    cudaGetSymbolAddress((void**)&Al, g_Al);
    cudaGetSymbolAddress((void**)&Bh, g_Bh);
    cudaGetSymbolAddress((void**)&Bl, g_Bl);

    const int TB = 256;
    detect_kernel<<<1, 256>>>((const int*)ei);
    build_edges_kernel<<<(ET + TB - 1) / TB, TB>>>(ei);
    hist_kernel<<<(ET + TB - 1) / TB, TB>>>();
    csr_partial_kernel<<<NBLK, 256>>>();
    csr_scanb_kernel<<<1, 32>>>();
    csr_offsets_kernel<<<NBLK, 256>>>();
    scatter_kernel<<<(ET + TB - 1) / TB, TB>>>();
    pad_kernel<<<((MP - NN) * 256 + TB - 1) / TB, TB>>>();

    int alBlocks  = (NN * HEADS + TB - 1) / TB;
    int aggBlocks = (NN * 32 + TB - 1) / TB;
    const int MROWS = MP / 128;   // 157

    auto splitN = [&](const float* src, __nv_bfloat16* h, __nv_bfloat16* l,
                      int realE, int totE) {
        split_kernel<<<(totE / 4 + TB - 1) / TB, TB>>>(src, h, l, realE, totE);
    };

    // ---------------- layer 0 ----------------
    splitN(x, Ah, Al, NN * 64, MP * 64);
    splitN(W0, Bh, Bl, 64 * 256, 64 * 256);
    gemm_tc_kernel<<<dim3(2, MROWS), 256>>>(Ah, Al, Bh, Bl, feat, 256, 64);
    tohalf_kernel<<<(NN * 256 / 4 + TB - 1) / TB, TB>>>(feat, feath, NN * 256);
    splitN(rW0, Bh, Bl, 64 * 256, 64 * 256);
    gemm_tc_kernel<<<dim3(2, MROWS), 256>>>(Ah, Al, Bh, Bl, res, 256, 64);
    al_kernel<<<alBlocks, TB>>>(as0, ad0, 32);
    agg_small_kernel<<<aggBlocks, TB>>>(feath, accb);
    finalize01_kernel<<<NN, 256>>>(b0, lng0, lnb0, res, rb0, rw0, act0, Ah, Al);

    // ---------------- layer 1 ----------------
    splitN(W1, Bh, Bl, 256 * 256, 256 * 256);
    gemm_tc_kernel<<<dim3(2, MROWS), 256>>>(Ah, Al, Bh, Bl, feat, 256, 256);
    tohalf_kernel<<<(NN * 256 / 4 + TB - 1) / TB, TB>>>(feat, feath, NN * 256);
    al_kernel<<<alBlocks, TB>>>(as1, ad1, 32);
    agg_small_kernel<<<aggBlocks, TB>>>(feath, accb);
    finalize01_kernel<<<NN, 256>>>(b1, lng1, lnb1, act0, nullptr, rw1, act1, Ah, Al);

    // ---------------- layer 2 ----------------
    splitN(W2, Bh, Bl, 256 * 1024, 256 * 1024);
    gemm_tc_kernel<<<dim3(8, MROWS), 256>>>(Ah, Al, Bh, Bl, feat, 1024, 256);
    tohalf_kernel<<<(NN * 1024 / 4 + TB - 1) / TB, TB>>>(feat, feath, NN * 1024);
    splitN(rW2, Bh, Bl, 256 * 128, 256 * 128);
    gemm_tc_kernel<<<dim3(1, MROWS), 256>>>(Ah, Al, Bh, Bl, res, 128, 256);
    al_kernel<<<alBlocks, TB>>>(as2, ad2, 128);
    agg_big_kernel<<<aggBlocks, TB>>>(feath, accb);
    finalize2_kernel<<<NN, 128>>>(b2, lng2, lnb2, res, rb2, rw2, (float*)d_out);
}